// round 14
// baseline (speedup 1.0000x reference)
#include <cuda_runtime.h>

#define BSZ 32
#define NA  8400
#define NM  100
#define NC  80
#define TK  13
#define EPSF 1e-9f

// ---------------- scratch (__device__ globals; no allocation) ----------------
__device__ int   g_cnt[BSZ * NA];    // #gts claiming this anchor via topk
__device__ int   g_claim[BSZ * NA];  // claiming gt j (valid when cnt==1)
__device__ int   g_jm[BSZ * NA];     // final assigned gt (-1 = negative anchor)
__device__ float g_m[BSZ * NA];      // align metric at (jm, i)
__device__ int   g_pa[BSZ * NM];     // pos_align  (float bits, atomicMax)
__device__ int   g_po[BSZ * NM];     // pos_overlaps (float bits, atomicMax)

__device__ __forceinline__ float iou_f(float4 g, float4 p, float areaG, float areaP) {
    float lx = fmaxf(g.x, p.x), ly = fmaxf(g.y, p.y);
    float rx = fminf(g.z, p.z), ry = fminf(g.w, p.w);
    float w = fmaxf(rx - lx, 0.f), h = fmaxf(ry - ly, 0.f);
    float inter = w * h;
    return inter / ((areaG + areaP) - inter + EPSF);   // same assoc as reference
}

// ---------------- K0: init counters ----------------
__global__ void k_init() {
    int t = blockIdx.x * blockDim.x + threadIdx.x;
    if (t < BSZ * NA) g_cnt[t] = 0;
    if (t < BSZ * NM) { g_pa[t] = 0; g_po[t] = 0; }
}

// ---------------- K1: one WARP per (b,j), compacted candidate processing -----
// Scan is branchless: 4 anchors/lane/iter, ballot-compacted hit indices into a
// per-warp smem stack; the expensive metric+insert path runs only in full-warp
// batches of 32 candidates (all lanes active).
// key = (float_bits(metric)<<32) | ~i reproduces lax.top_k order (metric desc,
// index asc). Only metric>0 entries are kept: zero-metric topk winners are
// annihilated by is_in_gts in mask_pos downstream.
__global__ __launch_bounds__(256) void k_topk(
    const float* __restrict__ ps, const float* __restrict__ pb,
    const float* __restrict__ ap, const int* __restrict__ gl,
    const float* __restrict__ gb, const float* __restrict__ mg)
{
    const unsigned FULL = 0xFFFFFFFFu;
    int warp = threadIdx.x >> 5, lane = threadIdx.x & 31;
    int w = blockIdx.x * 8 + warp;            // w = b*NM + j, grid exact (3200)
    int b = w / NM, j = w - b * NM;

    __shared__ unsigned short stk[8][160];    // per-warp candidate stack
    unsigned short* st = stk[warp];

    if (mg[b * NM + j] <= 0.f) return;        // masked gt claims nothing

    float4 g = ((const float4*)gb)[b * NM + j];
    int   lab = gl[b * NM + j];
    float areaG = (g.z - g.x) * (g.w - g.y);
    const float*  psb = ps + ((size_t)b * NA) * NC + lab;
    const float4* pbb = ((const float4*)pb) + (size_t)b * NA;
    const float4* ap4 = (const float4*)ap;    // 2 anchor points per float4

    unsigned long long loc[TK];
#pragma unroll
    for (int k = 0; k < TK; k++) loc[k] = 0ull;

    const unsigned ltm = (1u << lane) - 1u;
    int cnt = 0;                               // warp-uniform stack depth

    // ---- branchless scan: 66 iters x 128 anchors (4/lane) ----
#pragma unroll 1
    for (int t = 0; t < 66; t++) {
        int i0 = t * 128 + lane * 4;
        bool v = (i0 < NA);                    // NA%4==0: all 4 valid together
        int li = v ? i0 : 0;
        float4 A = __ldg(&ap4[li >> 1]);       // anchors li, li+1
        float4 B = __ldg(&ap4[(li >> 1) + 1]); // anchors li+2, li+3

        float d0 = fminf(fminf(A.x - g.x, A.y - g.y), fminf(g.z - A.x, g.w - A.y));
        float d1 = fminf(fminf(A.z - g.x, A.w - g.y), fminf(g.z - A.z, g.w - A.w));
        float d2 = fminf(fminf(B.x - g.x, B.y - g.y), fminf(g.z - B.x, g.w - B.y));
        float d3 = fminf(fminf(B.z - g.x, B.w - g.y), fminf(g.z - B.z, g.w - B.w));
        bool h0 = v && (d0 > EPSF), h1 = v && (d1 > EPSF);
        bool h2 = v && (d2 > EPSF), h3 = v && (d3 > EPSF);

        unsigned b0 = __ballot_sync(FULL, h0);
        if (h0) st[cnt + __popc(b0 & ltm)] = (unsigned short)(i0 + 0);
        cnt += __popc(b0);
        unsigned b1 = __ballot_sync(FULL, h1);
        if (h1) st[cnt + __popc(b1 & ltm)] = (unsigned short)(i0 + 1);
        cnt += __popc(b1);
        unsigned b2 = __ballot_sync(FULL, h2);
        if (h2) st[cnt + __popc(b2 & ltm)] = (unsigned short)(i0 + 2);
        cnt += __popc(b2);
        unsigned b3 = __ballot_sync(FULL, h3);
        if (h3) st[cnt + __popc(b3 & ltm)] = (unsigned short)(i0 + 3);
        cnt += __popc(b3);

        // uniform branch: process full batches of 32 candidates, all lanes busy
        while (cnt >= 32) {
            cnt -= 32;
            int i = st[cnt + lane];
            float4 p = __ldg(&pbb[i]);
            float areaP = (p.z - p.x) * (p.w - p.y);
            float iou = iou_f(g, p, areaG, areaP);
            float s = __ldg(&psb[(size_t)i * NC]);
            float i2 = iou * iou;
            float metric = s * (i2 * i2 * i2);
            if (metric > 0.f) {
                unsigned long long key =
                    ((unsigned long long)__float_as_uint(metric) << 32) |
                    (unsigned)(~(unsigned)i);
                if (key > loc[TK - 1]) {
                    loc[TK - 1] = key;
#pragma unroll
                    for (int k = TK - 1; k > 0; k--) {
                        unsigned long long lo = loc[k], hi = loc[k - 1];
                        if (lo > hi) { loc[k - 1] = lo; loc[k] = hi; }
                    }
                }
            }
        }
    }

    // ---- tail: cnt < 32 remaining candidates ----
    if (cnt > 0) {
        bool act = (lane < cnt);
        int i = act ? st[lane] : st[0];
        float4 p = __ldg(&pbb[i]);
        float areaP = (p.z - p.x) * (p.w - p.y);
        float iou = iou_f(g, p, areaG, areaP);
        float s = __ldg(&psb[(size_t)i * NC]);
        float i2 = iou * iou;
        float metric = s * (i2 * i2 * i2);
        if (act && metric > 0.f) {
            unsigned long long key =
                ((unsigned long long)__float_as_uint(metric) << 32) |
                (unsigned)(~(unsigned)i);
            if (key > loc[TK - 1]) {
                loc[TK - 1] = key;
#pragma unroll
                for (int k = TK - 1; k > 0; k--) {
                    unsigned long long lo = loc[k], hi = loc[k - 1];
                    if (lo > hi) { loc[k - 1] = lo; loc[k] = hi; }
                }
            }
        }
    }

    // ---- warp merge: rounds of warp-argmax over per-lane sorted heads ----
    // Keys unique (embed ~i, each anchor processed once) -> one winner per round.
#pragma unroll 1
    for (int r = 0; r < TK; r++) {
        unsigned long long best = loc[0];
#pragma unroll
        for (int off = 16; off; off >>= 1) {
            unsigned long long o = __shfl_xor_sync(FULL, best, off);
            if (o > best) best = o;
        }
        if (best == 0ull) break;              // no positive candidates left
        unsigned ball = __ballot_sync(FULL, loc[0] == best);
        if (lane == __ffs(ball) - 1) {
            int idx = (int)(~(unsigned)(best & 0xFFFFFFFFull));
            atomicAdd(&g_cnt[b * NA + idx], 1);
            g_claim[b * NA + idx] = j;        // unique writer when cnt==1
#pragma unroll
            for (int k = 0; k < TK - 1; k++) loc[k] = loc[k + 1];
            loc[TK - 1] = 0ull;
        }
    }
}

// ---------------- K2: resolve assignment per anchor ----------------
__global__ __launch_bounds__(128) void k_assign(
    const float* __restrict__ ps, const float* __restrict__ pb,
    const float* __restrict__ gb, const int* __restrict__ gl)
{
    int b = blockIdx.y;
    __shared__ float4 sG[NM];
    __shared__ int    sL[NM];
    for (int t = threadIdx.x; t < NM; t += 128) {
        sG[t] = ((const float4*)gb)[b * NM + t];
        sL[t] = gl[b * NM + t];
    }
    __syncthreads();
    int i = blockIdx.x * 128 + threadIdx.x;
    if (i >= NA) return;
    int o = b * NA + i;
    int c = g_cnt[o];
    int jm = -1;
    float mval = 0.f;
    if (c > 0) {
        float4 p = ((const float4*)pb)[(size_t)b * NA + i];
        float areaP = (p.z - p.x) * (p.w - p.y);
        if (c == 1) {
            jm = g_claim[o];
        } else {
            // multi-claimed anchor -> first-argmax of IoU over ALL 100 gts
            float best = -1.f;
            for (int jj = 0; jj < NM; jj++) {
                float4 gg = sG[jj];
                float areaG = (gg.z - gg.x) * (gg.w - gg.y);
                float iou = iou_f(gg, p, areaG, areaP);
                if (iou > best) { best = iou; jm = jj; }
            }
        }
        float4 gg = sG[jm];
        float areaG = (gg.z - gg.x) * (gg.w - gg.y);
        float iou = iou_f(gg, p, areaG, areaP);
        float s = ps[(size_t)o * NC + sL[jm]];
        float i2 = iou * iou;
        mval = s * (i2 * i2 * i2);
        atomicMax(&g_pa[b * NM + jm], __float_as_int(mval));  // nonneg: int order ok
        atomicMax(&g_po[b * NM + jm], __float_as_int(iou));
    }
    g_jm[o] = jm;
    g_m[o]  = mval;
}

// ---------------- K3: fused finalize + coalesced scores ----------------
__global__ __launch_bounds__(256) void k_final(
    const float* __restrict__ gb, const int* __restrict__ gl,
    float* __restrict__ oL, float* __restrict__ oB,
    float* __restrict__ oS, float* __restrict__ oP)
{
    __shared__ int   sCls[64];
    __shared__ float sNrm[64];
    int b  = blockIdx.y;
    int a0 = blockIdx.x * 64;

    if (threadIdx.x < 64) {
        int i = a0 + threadIdx.x;
        if (i < NA) {
            int o = b * NA + i;
            int jm = g_jm[o];
            bool pos = (jm >= 0);
            int ag = pos ? jm : 0;            // argmax of all-zero column = 0
            int lab = gl[b * NM + ag];
            if (lab < 0) lab = 0;
            float nrm = 0.f;
            if (pos) {
                float pa = __int_as_float(g_pa[b * NM + jm]);
                float po = __int_as_float(g_po[b * NM + jm]);
                nrm = g_m[o] * po / (pa + EPSF);
            }
            if (oL) oL[o] = pos ? (float)lab : (float)NC;
            if (oB) ((float4*)oB)[o] = ((const float4*)gb)[b * NM + ag]; // unmasked (matches ref)
            if (oP) oP[o] = pos ? 1.f : 0.f;
            sCls[threadIdx.x] = pos ? lab : -1;
            sNrm[threadIdx.x] = nrm;
        }
    }
    __syncthreads();

    // 64 anchors * 20 float4 = 1280 coalesced stores
    float4* dst = ((float4*)oS) + ((size_t)b * NA + a0) * 20;
#pragma unroll
    for (int t = threadIdx.x; t < 64 * 20; t += 256) {
        int al = t / 20;
        if (a0 + al >= NA) break;
        int c0 = (t - al * 20) * 4;
        int cls = sCls[al];
        float nv = sNrm[al];
        float4 v = make_float4(0.f, 0.f, 0.f, 0.f);
        int d = cls - c0;
        if (d >= 0 && d < 4) {
            if      (d == 0) v.x = nv;
            else if (d == 1) v.y = nv;
            else if (d == 2) v.z = nv;
            else             v.w = nv;
        }
        dst[t] = v;
    }
}

// ---------------- launch ----------------
extern "C" void kernel_launch(void* const* d_in, const int* in_sizes, int n_in,
                              void* d_out, int out_size)
{
    const float* ps = (const float*)d_in[0];   // pred_scores  (32,8400,80)
    const float* pb = (const float*)d_in[1];   // pred_bboxes  (32,8400,4)
    const float* ap = (const float*)d_in[2];   // anchor_points(8400,2)
    const int*   gl = (const int*)  d_in[3];   // gt_labels    (32,100,1)
    const float* gb = (const float*)d_in[4];   // gt_bboxes    (32,100,4)
    const float* mg = (const float*)d_in[5];   // mask_gt      (32,100,1)

    float* out = (float*)d_out;
    float *oL = nullptr, *oB = nullptr, *oS = nullptr, *oP = nullptr;
    const int FULL_SZ = BSZ * NA * (1 + 4 + NC + 1);   // 23,116,800
    if (out_size == FULL_SZ) {
        oL = out;
        oB = out + BSZ * NA;
        oS = oB + BSZ * NA * 4;
        oP = oS + (size_t)BSZ * NA * NC;
    } else {
        oS = out;   // fallback: scores-only output
    }

    k_init<<<(BSZ * NA + 255) / 256, 256>>>();
    k_topk<<<BSZ * NM / 8, 256>>>(ps, pb, ap, gl, gb, mg);
    k_assign<<<dim3((NA + 127) / 128, BSZ), 128>>>(ps, pb, gb, gl);
    k_final<<<dim3((NA + 63) / 64, BSZ), 256>>>(gb, gl, oL, oB, oS, oP);
}

// round 15
// speedup vs baseline: 1.0124x; 1.0124x over previous
#include <cuda_runtime.h>

#define BSZ 32
#define NA  8400
#define NM  100
#define NC  80
#define TK  13
#define EPSF 1e-9f

// ---------------- scratch (__device__ globals; no allocation) ----------------
__device__ int   g_cnt[BSZ * NA];    // #gts claiming this anchor via topk
__device__ int   g_claim[BSZ * NA];  // claiming gt j (valid when cnt==1)
__device__ int   g_jm[BSZ * NA];     // final assigned gt (-1 = negative anchor)
__device__ float g_m[BSZ * NA];      // align metric at (jm, i)
__device__ int   g_pa[BSZ * NM];     // pos_align  (float bits, atomicMax)
__device__ int   g_po[BSZ * NM];     // pos_overlaps (float bits, atomicMax)

__device__ __forceinline__ float iou_f(float4 g, float4 p, float areaG, float areaP) {
    float lx = fmaxf(g.x, p.x), ly = fmaxf(g.y, p.y);
    float rx = fminf(g.z, p.z), ry = fminf(g.w, p.w);
    float w = fmaxf(rx - lx, 0.f), h = fmaxf(ry - ly, 0.f);
    float inter = w * h;
    return inter / ((areaG + areaP) - inter + EPSF);   // same assoc as reference
}

// ---------------- K0: init counters ----------------
__global__ void k_init() {
    int t = blockIdx.x * blockDim.x + threadIdx.x;
    if (t < BSZ * NA) g_cnt[t] = 0;
    if (t < BSZ * NM) { g_pa[t] = 0; g_po[t] = 0; }
}

// ---------------- K1: one WARP per (b,j), pipelined scan + compaction --------
// Scan: 8 anchors/lane/iter via 4 LDG.128, next tile prefetched into registers
// before processing current (MLP≈8, hides L2 latency). Hits are ballot-compacted
// into a per-warp smem stack; the metric+insert path runs only in full-warp
// batches of 32 (all lanes active).
// key = (float_bits(metric)<<32) | ~i reproduces lax.top_k order (metric desc,
// index asc). Only metric>0 entries kept: zero-metric topk winners are
// annihilated by is_in_gts in mask_pos downstream.
__global__ __launch_bounds__(256) void k_topk(
    const float* __restrict__ ps, const float* __restrict__ pb,
    const float* __restrict__ ap, const int* __restrict__ gl,
    const float* __restrict__ gb, const float* __restrict__ mg)
{
    const unsigned FULL = 0xFFFFFFFFu;
    int warp = threadIdx.x >> 5, lane = threadIdx.x & 31;
    int w = blockIdx.x * 8 + warp;            // w = b*NM + j, grid exact (3200)
    int b = w / NM, j = w - b * NM;

    __shared__ unsigned short stk[8][288];    // per-warp candidate stack
    unsigned short* st = stk[warp];

    if (mg[b * NM + j] <= 0.f) return;        // masked gt claims nothing

    float4 g = ((const float4*)gb)[b * NM + j];
    int   lab = gl[b * NM + j];
    float areaG = (g.z - g.x) * (g.w - g.y);
    const float*  psb = ps + ((size_t)b * NA) * NC + lab;
    const float4* pbb = ((const float4*)pb) + (size_t)b * NA;
    const float4* ap4 = (const float4*)ap;    // 2 anchor points per float4

    unsigned long long loc[TK];
#pragma unroll
    for (int k = 0; k < TK; k++) loc[k] = 0ull;

    const unsigned ltm = (1u << lane) - 1u;
    int cnt = 0;                               // warp-uniform stack depth

    // ---- pipelined scan: 33 iters x 256 anchors (8/lane, 4 LDG.128) ----
    const int base = lane * 8;                 // lane offset inside 256-anchor tile
    // NITER*256 = 8448 > NA: last tile partially valid; v-mask per 8-group
    // (NA%8==0 so a group is all-valid or all-invalid). Clamp OOB addresses.
    int li0 = base;                            // tile 0 anchor index (always < NA)
    float4 A0 = __ldg(&ap4[(li0 >> 1) + 0]);
    float4 A1 = __ldg(&ap4[(li0 >> 1) + 1]);
    float4 A2 = __ldg(&ap4[(li0 >> 1) + 2]);
    float4 A3 = __ldg(&ap4[(li0 >> 1) + 3]);

#pragma unroll 1
    for (int t = 0; t < 33; t++) {
        float4 B0, B1, B2, B3;
        if (t < 32) {                          // prefetch next tile (uniform branch)
            int ni = (t + 1) * 256 + base;
            int nc_ = (ni < NA) ? ni : (NA - 8);   // clamp: garbage unused via v-mask
            B0 = __ldg(&ap4[(nc_ >> 1) + 0]);
            B1 = __ldg(&ap4[(nc_ >> 1) + 1]);
            B2 = __ldg(&ap4[(nc_ >> 1) + 2]);
            B3 = __ldg(&ap4[(nc_ >> 1) + 3]);
        }

        int i0 = t * 256 + base;
        bool v = (i0 < NA);

        float d0 = fminf(fminf(A0.x - g.x, A0.y - g.y), fminf(g.z - A0.x, g.w - A0.y));
        float d1 = fminf(fminf(A0.z - g.x, A0.w - g.y), fminf(g.z - A0.z, g.w - A0.w));
        float d2 = fminf(fminf(A1.x - g.x, A1.y - g.y), fminf(g.z - A1.x, g.w - A1.y));
        float d3 = fminf(fminf(A1.z - g.x, A1.w - g.y), fminf(g.z - A1.z, g.w - A1.w));
        float d4 = fminf(fminf(A2.x - g.x, A2.y - g.y), fminf(g.z - A2.x, g.w - A2.y));
        float d5 = fminf(fminf(A2.z - g.x, A2.w - g.y), fminf(g.z - A2.z, g.w - A2.w));
        float d6 = fminf(fminf(A3.x - g.x, A3.y - g.y), fminf(g.z - A3.x, g.w - A3.y));
        float d7 = fminf(fminf(A3.z - g.x, A3.w - g.y), fminf(g.z - A3.z, g.w - A3.w));

        float dd[8] = {d0, d1, d2, d3, d4, d5, d6, d7};
#pragma unroll
        for (int q = 0; q < 8; q++) {
            bool h = v && (dd[q] > EPSF);
            unsigned bl = __ballot_sync(FULL, h);
            if (h) st[cnt + __popc(bl & ltm)] = (unsigned short)(i0 + q);
            cnt += __popc(bl);
        }

        // uniform drain: full batches of 32 candidates, all lanes busy
        while (cnt >= 32) {
            cnt -= 32;
            int i = st[cnt + lane];
            float4 p = __ldg(&pbb[i]);
            float areaP = (p.z - p.x) * (p.w - p.y);
            float iou = iou_f(g, p, areaG, areaP);
            float s = __ldg(&psb[(size_t)i * NC]);
            float i2 = iou * iou;
            float metric = s * (i2 * i2 * i2);
            if (metric > 0.f) {
                unsigned long long key =
                    ((unsigned long long)__float_as_uint(metric) << 32) |
                    (unsigned)(~(unsigned)i);
                if (key > loc[TK - 1]) {
                    loc[TK - 1] = key;
#pragma unroll
                    for (int k = TK - 1; k > 0; k--) {
                        unsigned long long lo = loc[k], hi = loc[k - 1];
                        if (lo > hi) { loc[k - 1] = lo; loc[k] = hi; }
                    }
                }
            }
        }

        A0 = B0; A1 = B1; A2 = B2; A3 = B3;
    }

    // ---- tail: cnt < 32 remaining candidates ----
    if (cnt > 0) {
        bool act = (lane < cnt);
        int i = act ? st[lane] : st[0];
        float4 p = __ldg(&pbb[i]);
        float areaP = (p.z - p.x) * (p.w - p.y);
        float iou = iou_f(g, p, areaG, areaP);
        float s = __ldg(&psb[(size_t)i * NC]);
        float i2 = iou * iou;
        float metric = s * (i2 * i2 * i2);
        if (act && metric > 0.f) {
            unsigned long long key =
                ((unsigned long long)__float_as_uint(metric) << 32) |
                (unsigned)(~(unsigned)i);
            if (key > loc[TK - 1]) {
                loc[TK - 1] = key;
#pragma unroll
                for (int k = TK - 1; k > 0; k--) {
                    unsigned long long lo = loc[k], hi = loc[k - 1];
                    if (lo > hi) { loc[k - 1] = lo; loc[k] = hi; }
                }
            }
        }
    }

    // ---- warp merge: rounds of warp-argmax over per-lane sorted heads ----
    // Keys unique (embed ~i, each anchor processed once) -> one winner per round.
#pragma unroll 1
    for (int r = 0; r < TK; r++) {
        unsigned long long best = loc[0];
#pragma unroll
        for (int off = 16; off; off >>= 1) {
            unsigned long long o = __shfl_xor_sync(FULL, best, off);
            if (o > best) best = o;
        }
        if (best == 0ull) break;              // no positive candidates left
        unsigned ball = __ballot_sync(FULL, loc[0] == best);
        if (lane == __ffs(ball) - 1) {
            int idx = (int)(~(unsigned)(best & 0xFFFFFFFFull));
            atomicAdd(&g_cnt[b * NA + idx], 1);
            g_claim[b * NA + idx] = j;        // unique writer when cnt==1
#pragma unroll
            for (int k = 0; k < TK - 1; k++) loc[k] = loc[k + 1];
            loc[TK - 1] = 0ull;
        }
    }
}

// ---------------- K2: resolve assignment per anchor ----------------
__global__ __launch_bounds__(128) void k_assign(
    const float* __restrict__ ps, const float* __restrict__ pb,
    const float* __restrict__ gb, const int* __restrict__ gl)
{
    int b = blockIdx.y;
    __shared__ float4 sG[NM];
    __shared__ int    sL[NM];
    for (int t = threadIdx.x; t < NM; t += 128) {
        sG[t] = ((const float4*)gb)[b * NM + t];
        sL[t] = gl[b * NM + t];
    }
    __syncthreads();
    int i = blockIdx.x * 128 + threadIdx.x;
    if (i >= NA) return;
    int o = b * NA + i;
    int c = g_cnt[o];
    int jm = -1;
    float mval = 0.f;
    if (c > 0) {
        float4 p = ((const float4*)pb)[(size_t)b * NA + i];
        float areaP = (p.z - p.x) * (p.w - p.y);
        if (c == 1) {
            jm = g_claim[o];
        } else {
            // multi-claimed anchor -> first-argmax of IoU over ALL 100 gts
            float best = -1.f;
            for (int jj = 0; jj < NM; jj++) {
                float4 gg = sG[jj];
                float areaG = (gg.z - gg.x) * (gg.w - gg.y);
                float iou = iou_f(gg, p, areaG, areaP);
                if (iou > best) { best = iou; jm = jj; }
            }
        }
        float4 gg = sG[jm];
        float areaG = (gg.z - gg.x) * (gg.w - gg.y);
        float iou = iou_f(gg, p, areaG, areaP);
        float s = ps[(size_t)o * NC + sL[jm]];
        float i2 = iou * iou;
        mval = s * (i2 * i2 * i2);
        atomicMax(&g_pa[b * NM + jm], __float_as_int(mval));  // nonneg: int order ok
        atomicMax(&g_po[b * NM + jm], __float_as_int(iou));
    }
    g_jm[o] = jm;
    g_m[o]  = mval;
}

// ---------------- K3: fused finalize + coalesced scores ----------------
__global__ __launch_bounds__(256) void k_final(
    const float* __restrict__ gb, const int* __restrict__ gl,
    float* __restrict__ oL, float* __restrict__ oB,
    float* __restrict__ oS, float* __restrict__ oP)
{
    __shared__ int   sCls[64];
    __shared__ float sNrm[64];
    int b  = blockIdx.y;
    int a0 = blockIdx.x * 64;

    if (threadIdx.x < 64) {
        int i = a0 + threadIdx.x;
        if (i < NA) {
            int o = b * NA + i;
            int jm = g_jm[o];
            bool pos = (jm >= 0);
            int ag = pos ? jm : 0;            // argmax of all-zero column = 0
            int lab = gl[b * NM + ag];
            if (lab < 0) lab = 0;
            float nrm = 0.f;
            if (pos) {
                float pa = __int_as_float(g_pa[b * NM + jm]);
                float po = __int_as_float(g_po[b * NM + jm]);
                nrm = g_m[o] * po / (pa + EPSF);
            }
            if (oL) oL[o] = pos ? (float)lab : (float)NC;
            if (oB) ((float4*)oB)[o] = ((const float4*)gb)[b * NM + ag]; // unmasked (matches ref)
            if (oP) oP[o] = pos ? 1.f : 0.f;
            sCls[threadIdx.x] = pos ? lab : -1;
            sNrm[threadIdx.x] = nrm;
        }
    }
    __syncthreads();

    // 64 anchors * 20 float4 = 1280 coalesced stores
    float4* dst = ((float4*)oS) + ((size_t)b * NA + a0) * 20;
#pragma unroll
    for (int t = threadIdx.x; t < 64 * 20; t += 256) {
        int al = t / 20;
        if (a0 + al >= NA) break;
        int c0 = (t - al * 20) * 4;
        int cls = sCls[al];
        float nv = sNrm[al];
        float4 v = make_float4(0.f, 0.f, 0.f, 0.f);
        int d = cls - c0;
        if (d >= 0 && d < 4) {
            if      (d == 0) v.x = nv;
            else if (d == 1) v.y = nv;
            else if (d == 2) v.z = nv;
            else             v.w = nv;
        }
        dst[t] = v;
    }
}

// ---------------- launch ----------------
extern "C" void kernel_launch(void* const* d_in, const int* in_sizes, int n_in,
                              void* d_out, int out_size)
{
    const float* ps = (const float*)d_in[0];   // pred_scores  (32,8400,80)
    const float* pb = (const float*)d_in[1];   // pred_bboxes  (32,8400,4)
    const float* ap = (const float*)d_in[2];   // anchor_points(8400,2)
    const int*   gl = (const int*)  d_in[3];   // gt_labels    (32,100,1)
    const float* gb = (const float*)d_in[4];   // gt_bboxes    (32,100,4)
    const float* mg = (const float*)d_in[5];   // mask_gt      (32,100,1)

    float* out = (float*)d_out;
    float *oL = nullptr, *oB = nullptr, *oS = nullptr, *oP = nullptr;
    const int FULL_SZ = BSZ * NA * (1 + 4 + NC + 1);   // 23,116,800
    if (out_size == FULL_SZ) {
        oL = out;
        oB = out + BSZ * NA;
        oS = oB + BSZ * NA * 4;
        oP = oS + (size_t)BSZ * NA * NC;
    } else {
        oS = out;   // fallback: scores-only output
    }

    k_init<<<(BSZ * NA + 255) / 256, 256>>>();
    k_topk<<<BSZ * NM / 8, 256>>>(ps, pb, ap, gl, gb, mg);
    k_assign<<<dim3((NA + 127) / 128, BSZ), 128>>>(ps, pb, gb, gl);
    k_final<<<dim3((NA + 63) / 64, BSZ), 256>>>(gb, gl, oL, oB, oS, oP);
}